// round 7
// baseline (speedup 1.0000x reference)
#include <cuda_runtime.h>
#include <cstdint>

// Problem constants (from reference): B=8, N=65536, C=256, NPOINT=1024
#define BB        8
#define NN        65536
#define CC        256
#define NPOINTS   1024
#define CHUNKS    16                  // CTAs per batch == cluster size
#define TFPS      512                 // threads per FPS block
#define NWARP     (TFPS / 32)
#define PPB       (NN / CHUNKS)       // 4096 points per block
#define PPT       (PPB / TFPS)        // 8 points per thread

__device__ int g_inds[BB][NPOINTS];   // fully rewritten every run -> no init needed

struct InitFar { int v[BB]; };

// ---------------------------------------------------------------------------
// PTX helpers
// ---------------------------------------------------------------------------
__device__ __forceinline__ uint32_t smem_u32(const void* p) {
    uint32_t a;
    asm("{ .reg .u64 t; cvta.to.shared.u64 t, %1; cvt.u32.u64 %0, t; }" : "=r"(a) : "l"(p));
    return a;
}
__device__ __forceinline__ uint32_t my_ctarank() {
    uint32_t r; asm("mov.u32 %0, %%cluster_ctarank;" : "=r"(r)); return r;
}
__device__ __forceinline__ uint32_t mapa_u32(uint32_t local, uint32_t rank) {
    uint32_t r;
    asm("mapa.shared::cluster.u32 %0, %1, %2;" : "=r"(r) : "r"(local), "r"(rank));
    return r;
}
__device__ __forceinline__ void st_cl_relaxed(uint32_t a, unsigned long long v) {
    asm volatile("st.relaxed.cluster.shared::cluster.u64 [%0], %1;" :: "r"(a), "l"(v) : "memory");
}
__device__ __forceinline__ void st_cl_release(uint32_t a, unsigned long long v) {
    asm volatile("st.release.cluster.shared::cluster.u64 [%0], %1;" :: "r"(a), "l"(v) : "memory");
}
__device__ __forceinline__ unsigned long long ld_acq_cluster(uint32_t a) {
    unsigned long long v;
    asm volatile("ld.acquire.cluster.shared::cta.u64 %0, [%1];" : "=l"(v) : "r"(a) : "memory");
    return v;
}
__device__ __forceinline__ unsigned long long ld_smem_vol_u64(uint32_t a) {
    unsigned long long v;
    asm volatile("ld.volatile.shared.u64 %0, [%1];" : "=l"(v) : "r"(a) : "memory");
    return v;
}
__device__ __forceinline__ unsigned redux_max_u32(unsigned v) {
    unsigned r;
    asm volatile("redux.sync.max.u32 %0, %1, 0xffffffff;" : "=r"(r) : "r"(v));
    return r;
}
__device__ __forceinline__ void cluster_sync_all() {
    asm volatile("barrier.cluster.arrive.aligned;" ::: "memory");
    asm volatile("barrier.cluster.wait.aligned;"   ::: "memory");
}

// ---------------------------------------------------------------------------
// FPS: one batch = one 16-CTA cluster. Points + running distances live in
// registers. Per iteration:
//   compute + per-thread argmax
//   warp argmax via 2x redux.sync.max.u32 (dist bits, then tie-key)
//   winning lane writes (key, x, y, z) to shared
//   warp 0: block argmax (2x redux) -> DSMEM all-to-all publish of
//           24B payload {A=key+phase, B=(x,y), C=z} with release/acquire
//   warp 0: poll own 16 slots (LDS latency), 2x redux, broadcast winner
//           index + coordinates via shared.
// ZERO global memory reads on the critical path (coordinates ride along).
//
// Key format: A = dist_bits(32) ## lo, lo = (ienc & 0x7FFFFFFF) | phase<<31,
// ienc = ~idx. dist >= 0 -> bits order-preserving; within an iteration all
// values share the phase bit -> u64 max == (max dist, then smallest idx) ==
// jnp.argmax first-occurrence tie-break. Double buffering (it&1) + phase tag
// ((it>>1)&1) makes stale slot values self-identifying (peers are at most one
// iteration ahead by the data dependency). B,C stored relaxed BEFORE A's
// release store; poller acquires A, then reads B,C -> message-passing order.
// ---------------------------------------------------------------------------
__global__ __launch_bounds__(TFPS, 1) __cluster_dims__(CHUNKS, 1, 1)
void fps_kernel(const float* __restrict__ xyz, InitFar init) {
    const int b    = blockIdx.y;
    const int t    = threadIdx.x;
    const int lane = t & 31;
    const int warp = t >> 5;
    const uint32_t rank = my_ctarank();          // == blockIdx.x
    const int base = (int)rank * PPB;

    __shared__ unsigned long long s_cl[2][CHUNKS][4];  // {A,B,C,pad} 32B/slot
    __shared__ uint4 s_red[NWARP];                     // {dist, key, x, y}
    __shared__ float s_redz[NWARP];
    __shared__ uint4 s_bc;                             // {far, x, y, z}

    // Tag slots invalid for iterations 0/1 (they expect phase==0)
    if (t < 2 * CHUNKS) s_cl[t >> 4][t & 15][0] = 0x80000000ull;

    const float* __restrict__ xb = xyz + (size_t)b * NN * 3;

    float    px[PPT], py[PPT], pz[PPT], dist[PPT];
    unsigned ienc[PPT];
#pragma unroll
    for (int k = 0; k < PPT; ++k) {
        const int p = base + k * TFPS + t;
        const float* q = xb + 3 * (size_t)p;
        px[k] = q[0]; py[k] = q[1]; pz[k] = q[2];
        dist[k] = 1e10f;
        ienc[k] = ~(unsigned)p;
    }

    // DSMEM addresses (warp 0, lanes < CHUNKS)
    uint32_t pubA[2], pollA[2];
    {
        const uint32_t peer = (lane < CHUNKS) ? (uint32_t)lane : 0u;
        pubA[0] = mapa_u32(smem_u32(&s_cl[0][rank][0]), peer);
        pubA[1] = mapa_u32(smem_u32(&s_cl[1][rank][0]), peer);
        pollA[0] = smem_u32(&s_cl[0][lane & 15][0]);
        pollA[1] = smem_u32(&s_cl[1][lane & 15][0]);
    }

    __syncthreads();
    cluster_sync_all();   // all CTAs' slot tags initialized before any publish

    int far = init.v[b];
    // One-time centroid fetch; afterwards coordinates arrive via the exchange.
    float cx = __ldg(xb + 3 * (size_t)far + 0);
    float cy = __ldg(xb + 3 * (size_t)far + 1);
    float cz = __ldg(xb + 3 * (size_t)far + 2);

    for (int it = 0; it < NPOINTS; ++it) {
        const int buf = it & 1;
        const unsigned phase = (unsigned)((it >> 1) & 1);

        if (rank == 0 && t == 0) g_inds[b][it] = far;   // lax.scan pre-update index

        float    bd = -1.0f;
        unsigned bi = 0u;
#pragma unroll
        for (int k = 0; k < PPT; ++k) {
            // Match XLA (no FP contraction): sub, mul, (d0+d1)+d2, all RN
            const float dx = __fsub_rn(px[k], cx);
            const float dy = __fsub_rn(py[k], cy);
            const float dz = __fsub_rn(pz[k], cz);
            const float d  = __fadd_rn(__fadd_rn(__fmul_rn(dx, dx), __fmul_rn(dy, dy)),
                                       __fmul_rn(dz, dz));
            const float nd = fminf(dist[k], d);
            dist[k] = nd;
            if (nd > bd) { bd = nd; bi = ienc[k]; }     // strict > keeps smallest idx
        }

        // Warp argmax via redux: dist bits, then tie-key (ienc: bigger==smaller idx)
        const unsigned d0 = __float_as_uint(bd);
        const unsigned m0 = redux_max_u32(d0);
        const unsigned c0 = (d0 == m0) ? bi : 0u;
        const unsigned w0 = redux_max_u32(c0);
        if (d0 == m0 && bi == w0) {                      // unique winning lane
            float wx = px[0], wy = py[0], wz = pz[0];
#pragma unroll
            for (int k = 1; k < PPT; ++k)
                if (ienc[k] == bi) { wx = px[k]; wy = py[k]; wz = pz[k]; }
            s_red[warp] = make_uint4(m0, w0, __float_as_uint(wx), __float_as_uint(wy));
            s_redz[warp] = wz;
        }
        __syncthreads();

        if (warp == 0) {
            // Block argmax over NWARP(16) entries
            unsigned d2 = 0u, k2 = 0u, xb2 = 0u, yb2 = 0u, zb2 = 0u;
            if (lane < NWARP) {
                const uint4 r = s_red[lane];
                d2 = r.x; k2 = r.y; xb2 = r.z; yb2 = r.w;
                zb2 = __float_as_uint(s_redz[lane]);
            }
            const unsigned m2 = redux_max_u32(d2);
            const unsigned c2 = (d2 == m2) ? k2 : 0u;
            const unsigned w2 = redux_max_u32(c2);
            const unsigned bal = __ballot_sync(0xFFFFFFFFu, (d2 == m2) && (k2 == w2)) & 0xFFFFu;
            const int src = __ffs(bal) - 1;
            const unsigned xw = __shfl_sync(0xFFFFFFFFu, xb2, src);
            const unsigned yw = __shfl_sync(0xFFFFFFFFu, yb2, src);
            const unsigned zw = __shfl_sync(0xFFFFFFFFu, zb2, src);

            // Publish this block's winner to every CTA's slot[buf][rank]
            const unsigned lo = (w2 & 0x7FFFFFFFu) | (phase << 31);
            const unsigned long long A = ((unsigned long long)m2 << 32) | lo;
            const unsigned long long B = ((unsigned long long)yw << 32) | xw;
            const unsigned long long C = (unsigned long long)zw;
            if (lane < CHUNKS) {
                st_cl_relaxed(pubA[buf] + 8,  B);
                st_cl_relaxed(pubA[buf] + 16, C);
                st_cl_release(pubA[buf], A);            // orders B,C before A
            }

            // Poll own slots: lane r watches slot[buf][r] (LDS-latency rounds)
            unsigned long long a = 0ull;
            bool done = (lane >= CHUNKS);
            for (;;) {
                if (!done) {
                    a = ld_acq_cluster(pollA[buf]);
                    done = (((unsigned)(a >> 31)) & 1u) == phase;
                }
                if (__ballot_sync(0xFFFFFFFFu, done) == 0xFFFFFFFFu) break;
            }

            unsigned d3 = 0u, k3 = 0u, xr = 0u, yr = 0u, zr = 0u;
            if (lane < CHUNKS) {
                d3 = (unsigned)(a >> 32); k3 = (unsigned)a;
                const unsigned long long Br = ld_smem_vol_u64(pollA[buf] + 8);
                const unsigned long long Cr = ld_smem_vol_u64(pollA[buf] + 16);
                xr = (unsigned)Br; yr = (unsigned)(Br >> 32); zr = (unsigned)Cr;
            }
            const unsigned m3 = redux_max_u32(d3);
            const unsigned c3 = (d3 == m3) ? k3 : 0u;
            const unsigned w3 = redux_max_u32(c3);
            const unsigned bal3 = __ballot_sync(0xFFFFFFFFu, (d3 == m3) && (k3 == w3)) & 0xFFFFu;
            const int src3 = __ffs(bal3) - 1;
            const unsigned fx = __shfl_sync(0xFFFFFFFFu, xr, src3);
            const unsigned fy = __shfl_sync(0xFFFFFFFFu, yr, src3);
            const unsigned fz = __shfl_sync(0xFFFFFFFFu, zr, src3);
            if (lane == 0)
                s_bc = make_uint4((~w3) & 0xFFFFu, fx, fy, fz);
        }
        __syncthreads();
        const uint4 bc = s_bc;
        far = (int)bc.x;
        cx = __uint_as_float(bc.y);
        cy = __uint_as_float(bc.z);
        cz = __uint_as_float(bc.w);
    }

    cluster_sync_all();   // no CTA exits while peers might still address its SMEM
}

// ---------------------------------------------------------------------------
// Gather outputs. d_out (float32) layout, concatenated in reference order:
//   [0)                    new_xyz      (B, NPOINT, 3)
//   [B*NPOINT*3)           new_features (B, C, NPOINT)
//   [.. + B*C*NPOINT)      sample_inds  (B, NPOINT)  (indices as float)
// ---------------------------------------------------------------------------
__global__ void gather_kernel(const float* __restrict__ xyz,
                              const float* __restrict__ feat,
                              float* __restrict__ out) {
    const int b = blockIdx.x;
    const int c = blockIdx.y;

    float* out_xyz  = out;
    float* out_feat = out + (size_t)BB * NPOINTS * 3;
    float* out_inds = out_feat + (size_t)BB * CC * NPOINTS;

    const float* frow = feat + ((size_t)b * CC + c) * NN;
    float*       orow = out_feat + ((size_t)b * CC + c) * NPOINTS;

    for (int j = threadIdx.x; j < NPOINTS; j += blockDim.x) {
        const int idx = g_inds[b][j];
        orow[j] = __ldg(frow + idx);
        if (c == 0) {
            out_inds[(size_t)b * NPOINTS + j] = (float)idx;
            const float* q = xyz + ((size_t)b * NN + idx) * 3;
            float* o = out_xyz + ((size_t)b * NPOINTS + j) * 3;
            o[0] = __ldg(q + 0); o[1] = __ldg(q + 1); o[2] = __ldg(q + 2);
        }
    }
}

// ---------------------------------------------------------------------------
// Host: reproduce jax.random.randint(jax.random.key(1), (8,), 0, 65536)
// under jax_threefry_partitionable=True (default since JAX 0.5.0).
//   k1, k2 = split(key(1));  lower = random_bits(k2, 32, (8,));  idx = lower & 0xFFFF
//   split:       newkey_j = threefry2x32((0,1), (0, j))
//   random_bits: bits[b]  = o0 ^ o1 of threefry2x32(k2, (0, b))
// ---------------------------------------------------------------------------
static void threefry2x32_host(uint32_t k0, uint32_t k1, uint32_t c0, uint32_t c1,
                              uint32_t* o0, uint32_t* o1) {
    const uint32_t ks[3] = { k0, k1, k0 ^ k1 ^ 0x1BD11BDAu };
    static const int rot0[4] = {13, 15, 26, 6};
    static const int rot1[4] = {17, 29, 16, 24};
    uint32_t x0 = c0 + ks[0];
    uint32_t x1 = c1 + ks[1];
    for (int i = 0; i < 5; ++i) {
        const int* rr = (i % 2 == 0) ? rot0 : rot1;
        for (int j = 0; j < 4; ++j) {
            x0 += x1;
            x1 = (x1 << rr[j]) | (x1 >> (32 - rr[j]));
            x1 ^= x0;
        }
        x0 += ks[(i + 1) % 3];
        x1 += ks[(i + 2) % 3] + (uint32_t)(i + 1);
    }
    *o0 = x0; *o1 = x1;
}

extern "C" void kernel_launch(void* const* d_in, const int* in_sizes, int n_in,
                              void* d_out, int out_size) {
    (void)in_sizes; (void)n_in; (void)out_size;
    const float* xyz  = (const float*)d_in[0];
    const float* feat = (const float*)d_in[1];

    uint32_t k2a, k2b;
    threefry2x32_host(0u, 1u, 0u, 1u, &k2a, &k2b);   // k2 = second split of key(1)

    InitFar init;
    for (int b = 0; b < BB; ++b) {
        uint32_t o0, o1;
        threefry2x32_host(k2a, k2b, 0u, (uint32_t)b, &o0, &o1);
        init.v[b] = (int)((o0 ^ o1) & 0xFFFFu);
    }

    // 16-CTA clusters require the non-portable opt-in (idempotent, not captured)
    cudaFuncSetAttribute(fps_kernel, cudaFuncAttributeNonPortableClusterSizeAllowed, 1);

    fps_kernel<<<dim3(CHUNKS, BB), TFPS>>>(xyz, init);
    gather_kernel<<<dim3(BB, CC), 256>>>(xyz, feat, (float*)d_out);
}